// round 6
// baseline (speedup 1.0000x reference)
#include <cuda_runtime.h>
#include <math.h>
#include <stdint.h>

// ContextWindow: out[b, t, c*11 + i] = x[b, t+i-5, c] (zero pad in t),
// masked by t < round(2000 * lengths[b]).
// x: [32, 2000, 80] f32, lengths: [32] f32, out: [32, 2000, 880] f32.

#define B_    32
#define T_    2000
#define C_    80
#define C4_   20
#define CTX_  11
#define TT_   32
#define SROWS (TT_ + 10)       // 42
#define SPAD  84               // 16B-aligned rows; bank key (20i+c)%32: max 2-way
#define TILES_TOTAL 2016       // 63 t-tiles * 32 batches
#define J4_   (C_ * CTX_ / 4)  // 220
#define NTHR  224
#define NBLK  (TILES_TOTAL / 2)  // 1008: each block owns tiles B and 2015-B

__device__ __forceinline__ void cp16(uint32_t dst, const void* src, int sz) {
    asm volatile("cp.async.cg.shared.global [%0], [%1], 16, %2;"
                 :: "r"(dst), "l"(src), "r"(sz) : "memory");
}
__device__ __forceinline__ void cp_commit() {
    asm volatile("cp.async.commit_group;" ::: "memory");
}
__device__ __forceinline__ void cp_wait0() {
    asm volatile("cp.async.wait_group 0;" ::: "memory");
}

// Issue async fill of one tile (halo rows zero-filled via src-size 0).
__device__ __forceinline__ void prefetch_tile(
    float* sbuf, const float* __restrict__ x, int b, int t0, int v, int tid)
{
    if (v <= 0) return;                         // block-uniform
    const int n4 = (v + 10) * C4_;              // <= 840 float4
    const uint32_t sb = (uint32_t)__cvta_generic_to_shared(sbuf);
#pragma unroll 1
    for (int idx = tid; idx < n4; idx += NTHR) {
        const int r  = idx / C4_;
        const int c4 = idx - r * C4_;
        const int t  = t0 + r - 5;
        const int ok = (t >= 0 && t < T_);
        const int tc = ok ? t : 0;
        const float4* src = reinterpret_cast<const float4*>(x)
                          + ((size_t)b * T_ + tc) * C4_ + c4;
        cp16(sb + (uint32_t)(r * SPAD + c4 * 4) * 4u, src, ok ? 16 : 0);
    }
}

// Gather from smem + streaming stores (no barriers inside).
__device__ __forceinline__ void process_tile(
    const float* __restrict__ s, float* __restrict__ out,
    int b, int t0, int v, int n_stop, int j4)
{
    if (j4 >= J4_) return;

    const int j  = 4 * j4;
    int c0 = j / CTX_,  i0 = j - CTX_ * c0;
    int c1 = c0, i1 = i0 + 1; if (i1 == CTX_) { i1 = 0; c1++; }
    int c2 = c1, i2 = i1 + 1; if (i2 == CTX_) { i2 = 0; c2++; }
    int c3 = c2, i3 = i2 + 1; if (i3 == CTX_) { i3 = 0; c3++; }

    const float* p0 = &s[i0 * SPAD + c0];
    const float* p1 = &s[i1 * SPAD + c1];
    const float* p2 = &s[i2 * SPAD + c2];
    const float* p3 = &s[i3 * SPAD + c3];

    float4* outp = reinterpret_cast<float4*>(out)
                 + ((size_t)b * T_ + t0) * J4_ + j4;

    int tl = 0;
#pragma unroll 1
    for (; tl + 4 <= v; tl += 4) {
        float r[16];
#pragma unroll
        for (int u = 0; u < 4; u++) {
            const int o = (tl + u) * SPAD;
            r[4*u + 0] = p0[o];
            r[4*u + 1] = p1[o];
            r[4*u + 2] = p2[o];
            r[4*u + 3] = p3[o];
        }
#pragma unroll
        for (int u = 0; u < 4; u++)
            __stcs(outp + (size_t)u * J4_,
                   make_float4(r[4*u], r[4*u + 1], r[4*u + 2], r[4*u + 3]));
        outp += (size_t)4 * J4_;
    }
#pragma unroll 1
    for (; tl < v; tl++) {
        const int o = tl * SPAD;
        __stcs(outp, make_float4(p0[o], p1[o], p2[o], p3[o]));
        outp += J4_;
    }

    const float4 z = make_float4(0.f, 0.f, 0.f, 0.f);
#pragma unroll 1
    for (; tl + 4 <= n_stop; tl += 4) {
#pragma unroll
        for (int u = 0; u < 4; u++)
            __stcs(outp + (size_t)u * J4_, z);
        outp += (size_t)4 * J4_;
    }
#pragma unroll 1
    for (; tl < n_stop; tl++) {
        __stcs(outp, z);
        outp += J4_;
    }
}

__global__ __launch_bounds__(NTHR) void context_window_kernel(
    const float* __restrict__ x,
    const float* __restrict__ lengths,
    float* __restrict__ out)
{
    __shared__ float s[2][SROWS * SPAD];

    const int tid = threadIdx.x;

    // Two tiles per block, paired heavy+light: tau0 = B, tau1 = 2015 - B.
    int bA[2], t0A[2], vA[2], nsA[2];
#pragma unroll
    for (int k = 0; k < 2; k++) {
        const int tau = (k == 0) ? blockIdx.x : (TILES_TOTAL - 1 - blockIdx.x);
        const int b   = tau & 31;              // t-major: low t0 = heavy
        const int t0  = (tau >> 5) * TT_;
        // jnp.round == round-half-to-even == rintf
        const int len_abs = (int)rintf((float)T_ * lengths[b]);
        const int n_stop  = min(TT_, T_ - t0);
        bA[k]  = b;
        t0A[k] = t0;
        nsA[k] = n_stop;
        vA[k]  = min(max(len_abs - t0, 0), n_stop);
    }

    // Stage 0 fill
    prefetch_tile(s[0], x, bA[0], t0A[0], vA[0], tid);
    cp_commit();

#pragma unroll
    for (int k = 0; k < 2; k++) {
        cp_wait0();
        __syncthreads();
        if (k == 0) {
            // fire tile 1's fill; it completes while we store tile 0
            prefetch_tile(s[1], x, bA[1], t0A[1], vA[1], tid);
            cp_commit();
        }
        process_tile(s[k], out, bA[k], t0A[k], vA[k], nsA[k], tid);
    }
}

extern "C" void kernel_launch(void* const* d_in, const int* in_sizes, int n_in,
                              void* d_out, int out_size)
{
    const float* x       = (const float*)d_in[0];
    const float* lengths = (const float*)d_in[1];
    float* out           = (float*)d_out;

    (void)in_sizes; (void)n_in; (void)out_size;

    dim3 grid(NBLK);     // 1008 blocks, 2 paired tiles each
    dim3 block(NTHR);
    context_window_kernel<<<grid, block>>>(x, lengths, out);
}

// round 7
// speedup vs baseline: 1.0182x; 1.0182x over previous
#include <cuda_runtime.h>
#include <math.h>

// ContextWindow: out[b, t, c*11 + i] = x[b, t+i-5, c] (zero pad in t),
// masked by t < round(2000 * lengths[b]).
// x: [32, 2000, 80] f32, lengths: [32] f32, out: [32, 2000, 880] f32.

#define B_    32
#define T_    2000
#define C_    80
#define C4_   20              // float4 per x row
#define CTX_  11
#define TT_   40              // t-rows per block: 2000 = 50 * 40, uniform tiles
#define SROWS (TT_ + 10)      // 50 smem rows
#define SPAD  84              // 16B-aligned rows; bank key (20i+c)%32: ~2-way
#define SPAD4 21              // SPAD / 4
#define TILES 50
#define J4_   (C_ * CTX_ / 4) // 220 float4 per output row
#define NTHR  224

__global__ __launch_bounds__(NTHR) void context_window_kernel(
    const float* __restrict__ x,
    const float* __restrict__ lengths,
    float* __restrict__ out)
{
    __shared__ float s[SROWS * SPAD];

    const int blk = blockIdx.x;
    const int b   = blk & 31;            // t-major: heavy (low t0) blocks first
    const int t0  = (blk >> 5) * TT_;

    // jnp.round == round-half-to-even == rintf
    const int len_abs = (int)rintf((float)T_ * lengths[b]);
    const int v       = min(max(len_abs - t0, 0), TT_);   // non-zero rows

    // ---- Fill smem tile + halo with float4 loads ----
    if (v > 0) {
        const int n4 = (v + 10) * C4_;                    // <= 1000 float4
        const float4* __restrict__ x4 =
            reinterpret_cast<const float4*>(x) + ((size_t)b * T_ + t0 - 5) * C4_;
        float4* __restrict__ s4 = reinterpret_cast<float4*>(s);

        const bool edge = (t0 == 0) || (t0 + TT_ == T_);

        if (!edge) {
#pragma unroll 1
            for (int base = threadIdx.x; base < n4; base += 4 * NTHR) {
                float4 val[4];
#pragma unroll
                for (int u = 0; u < 4; u++) {
                    const int idx = base + u * NTHR;
                    if (idx < n4) val[u] = x4[idx];
                }
#pragma unroll
                for (int u = 0; u < 4; u++) {
                    const int idx = base + u * NTHR;
                    if (idx < n4) {
                        const int r  = idx / C4_;
                        const int c4 = idx - r * C4_;
                        s4[r * SPAD4 + c4] = val[u];
                    }
                }
            }
        } else {
#pragma unroll 1
            for (int idx = threadIdx.x; idx < n4; idx += NTHR) {
                const int r = idx / C4_;
                const int c4 = idx - r * C4_;
                const int t = t0 + r - 5;
                float4 val = make_float4(0.f, 0.f, 0.f, 0.f);
                if (t >= 0 && t < T_) val = x4[idx];
                s4[r * SPAD4 + c4] = val;
            }
        }
    }
    __syncthreads();   // guard is block-uniform

    const int j4 = threadIdx.x;
    if (j4 >= J4_) return;

    // ---- Fixed per-thread (c,i) mapping for j = 4*j4 .. 4*j4+3 ----
    const int j  = 4 * j4;
    int c0 = j / CTX_,  i0 = j - CTX_ * c0;
    int c1 = c0, i1 = i0 + 1; if (i1 == CTX_) { i1 = 0; c1++; }
    int c2 = c1, i2 = i1 + 1; if (i2 == CTX_) { i2 = 0; c2++; }
    int c3 = c2, i3 = i2 + 1; if (i3 == CTX_) { i3 = 0; c3++; }

    const float* p0 = &s[i0 * SPAD + c0];
    const float* p1 = &s[i1 * SPAD + c1];
    const float* p2 = &s[i2 * SPAD + c2];
    const float* p3 = &s[i3 * SPAD + c3];

    float4* outp = reinterpret_cast<float4*>(out)
                 + ((size_t)b * T_ + t0) * J4_ + j4;

    int tl = 0;

    // ---- Valid rows, 4 at a time: 16 independent LDS, then 4 STG.128 ----
#pragma unroll 1
    for (; tl + 4 <= v; tl += 4) {
        float r[16];
#pragma unroll
        for (int u = 0; u < 4; u++) {
            const int o = (tl + u) * SPAD;
            r[4*u + 0] = p0[o];
            r[4*u + 1] = p1[o];
            r[4*u + 2] = p2[o];
            r[4*u + 3] = p3[o];
        }
#pragma unroll
        for (int u = 0; u < 4; u++)
            __stcs(outp + (size_t)u * J4_,
                   make_float4(r[4*u], r[4*u + 1], r[4*u + 2], r[4*u + 3]));
        outp += (size_t)4 * J4_;
    }

    // ---- Remaining valid rows ----
#pragma unroll 1
    for (; tl < v; tl++) {
        const int o = tl * SPAD;
        __stcs(outp, make_float4(p0[o], p1[o], p2[o], p3[o]));
        outp += J4_;
    }

    // ---- Masked tail rows: pure streaming zero stores, 8 rows/iter ----
    const float4 z = make_float4(0.f, 0.f, 0.f, 0.f);
#pragma unroll 1
    for (; tl + 8 <= TT_; tl += 8) {
#pragma unroll
        for (int u = 0; u < 8; u++)
            __stcs(outp + (size_t)u * J4_, z);
        outp += (size_t)8 * J4_;
    }
#pragma unroll 1
    for (; tl < TT_; tl++) {
        __stcs(outp, z);
        outp += J4_;
    }
}

extern "C" void kernel_launch(void* const* d_in, const int* in_sizes, int n_in,
                              void* d_out, int out_size)
{
    const float* x       = (const float*)d_in[0];
    const float* lengths = (const float*)d_in[1];
    float* out           = (float*)d_out;

    (void)in_sizes; (void)n_in; (void)out_size;

    dim3 grid(TILES * B_);   // 50 t-tiles x 32 batches, t-major heavy-first
    dim3 block(NTHR);
    context_window_kernel<<<grid, block>>>(x, lengths, out);
}